// round 15
// baseline (speedup 1.0000x reference)
#include <cuda_runtime.h>

// Fixed problem shapes: B=4, L=80000, N=512, F=257, STRIDE=256 -> T=311
#define NB  4
#define NL  80000
#define NN  512
#define NF  257
#define NT  311
#define BFT (NB * NF * NT)   // 319708

#define TWO_PI 6.2831853071795864769f

__device__ __forceinline__ int bitrev4r(int v) {
    return ((v & 1) << 3) | ((v & 2) << 1) | ((v & 4) >> 1) | ((v & 8) >> 3);
}
__device__ __forceinline__ int bitrev5r(int v) {
    return ((v & 1) << 4) | ((v & 2) << 2) | (v & 4) | ((v & 8) >> 2) | ((v & 16) >> 4);
}
// position <-> frequency (9-bit reversal), pos = 32r + l
__device__ __forceinline__ int bitrev9r(int v) {
    return bitrev4r(v >> 5) | (bitrev5r(v & 31) << 4);
}

// ---------------------------------------------------------------------------
// Block = 512 threads (16 warps) per (frame t, batch-PAIR p); grid (NT, 2).
// Real-pair packing: z = g_{2p} + i*g_{2p+1}; one complex 512-FFT serves two
// batches. Thread tid owns position n = tid throughout.
//  Exchange #1 (H=256+128 fused radix-4, verified): q = tid>>7 warp-uniform,
//    quartet {j, j+128, j+256, j+384}, j = tid&127, wA = e^{-2pi*i*j/512}.
//  Exchange #2 (H=64+32, same fused formula per 128-block): q2 = (tid>>5)&3,
//    quartet {j2, j2+32, j2+64, j2+96} within the block, j2 = lane,
//    wA' = e^{-2pi*i*l/128}.
//  Shfl stages H=16..1 on one register.
//  Unpack: f = bitrev9(tid); threads with f <= 256 emit both batches:
//    F0 = (Z[f]+conj(Z[fb]))/2, F1 = -i*(Z[f]-conj(Z[fb]))/2, fb = (512-f)&511.
// Output layout: floats [0,BFT) = spec; [BFT,2*BFT) = real(stft).
// ---------------------------------------------------------------------------
__global__ void __launch_bounds__(512, 4)
adstft_kernel(const float* __restrict__ x,
              const float* __restrict__ wlp,
              const float* __restrict__ stp,
              float* __restrict__ out) {
    __shared__ float2 s1[512];   // input / (later) Z stash
    __shared__ float2 s2[512];   // exchange-#2 buffer

    const int tid = threadIdx.x;
    const int t = blockIdx.x;
    const int p = blockIdx.y;    // batch pair: batches 2p, 2p+1
    const int l = tid & 31;

    const float wl = fminf(fmaxf(wlp[0], 25.6f), 512.0f);   // WIN_MIN..WIN_MAX
    const float st = fminf(fmaxf(stp[0], 0.0f), 512.0f);    // STRIDE_MIN..MAX
    const float frame = st * (float)t;                       // == cumsum for integral st
    const float flo   = floorf(frame);
    const float frac  = frame - flo;
    const int   i0    = (int)flo;
    const float hi    = ceilf ((511.0f + wl) * 0.5f);
    const float lo    = floorf((511.0f - wl) * 0.5f);
    const float woff  = (wl - 511.0f) * 0.5f;

    // ---- Load + window: z = g_{2p} + i*g_{2p+1}, one point per thread ----
    {
        const float* xb0 = x + (2 * p) * NL;
        const float* xb1 = xb0 + NL;
        const int idx = i0 + tid;
        const bool ok = ((unsigned)idx < (unsigned)NL);
        const float v0 = ok ? xb0[idx] : 0.0f;
        const float v1 = ok ? xb1[idx] : 0.0f;
        const float base = (float)tid - frac;
        float tap = 0.0f;
        if (!(base >= hi || base <= lo))
            tap = (0.5f - 0.5f * __cosf(TWO_PI * (base + woff) / wl))
                  * 0.00390625f;                             // / N * 2
        s1[tid] = make_float2(v0 * tap, v1 * tap);
    }
    __syncthreads();

    // ---- Exchange #1: fused radix-4 (H=256, H=128) ----
    float zr, zi;
    {
        const int j = tid & 127;
        const int q = tid >> 7;                    // warp-uniform
        float wAi, wAr;                            // wA = e^{-2*pi*i*j/512}
        __sincosf(-TWO_PI * (float)j * (1.0f / 512.0f), &wAi, &wAr);

        const float2 c0 = s1[j];
        const float2 c1 = s1[j + 128];
        const float2 c2 = s1[j + 256];
        const float2 c3 = s1[j + 384];
        const float s0r = c0.x + c2.x, s0i = c0.y + c2.y;
        const float s1r = c1.x + c3.x, s1i = c1.y + c3.y;
        const float d0r = c0.x - c2.x, d0i = c0.y - c2.y;
        const float d1r = c1.x - c3.x, d1i = c1.y - c3.y;

        if (q == 0) {                        // B0 = s0 + s1
            zr = s0r + s1r; zi = s0i + s1i;
        } else if (q == 1) {                 // B1 = (s0 - s1) * wA^2
            const float wBr = wAr * wAr - wAi * wAi;
            const float wBi = 2.0f * wAr * wAi;
            const float er = s0r - s1r, ei = s0i - s1i;
            zr = er * wBr - ei * wBi;
            zi = er * wBi + ei * wBr;
        } else if (q == 2) {                 // B2 = wA * (d0 - i*d1)
            const float er = d0r + d1i, ei = d0i - d1r;
            zr = er * wAr - ei * wAi;
            zi = er * wAi + ei * wAr;
        } else {                             // B3 = wA^3 * (d0 + i*d1)
            const float wBr = wAr * wAr - wAi * wAi;
            const float wBi = 2.0f * wAr * wAi;
            const float wCr = wAr * wBr - wAi * wBi;
            const float wCi = wAr * wBi + wAi * wBr;
            const float er = d0r - d1i, ei = d0i + d1r;
            zr = er * wCr - ei * wCi;
            zi = er * wCi + ei * wCr;
        }
    }
    s2[tid] = make_float2(zr, zi);
    __syncthreads();

    // ---- Exchange #2: fused radix-4 (H=64, H=32) within each 128-block ----
    {
        const int base = tid & ~127;
        const int q2 = (tid >> 5) & 3;             // warp-uniform
        float wAi, wAr;                            // wA' = e^{-2*pi*i*l/128}
        __sincosf(-TWO_PI * (float)l * (1.0f / 128.0f), &wAi, &wAr);

        const float2 c0 = s2[base + l];
        const float2 c1 = s2[base + l + 32];
        const float2 c2 = s2[base + l + 64];
        const float2 c3 = s2[base + l + 96];
        const float s0r = c0.x + c2.x, s0i = c0.y + c2.y;
        const float s1r = c1.x + c3.x, s1i = c1.y + c3.y;
        const float d0r = c0.x - c2.x, d0i = c0.y - c2.y;
        const float d1r = c1.x - c3.x, d1i = c1.y - c3.y;

        if (q2 == 0) {
            zr = s0r + s1r; zi = s0i + s1i;
        } else if (q2 == 1) {
            const float wBr = wAr * wAr - wAi * wAi;
            const float wBi = 2.0f * wAr * wAi;
            const float er = s0r - s1r, ei = s0i - s1i;
            zr = er * wBr - ei * wBi;
            zi = er * wBi + ei * wBr;
        } else if (q2 == 2) {
            const float er = d0r + d1i, ei = d0i - d1r;
            zr = er * wAr - ei * wAi;
            zi = er * wAi + ei * wAr;
        } else {
            const float wBr = wAr * wAr - wAi * wAi;
            const float wBi = 2.0f * wAr * wAi;
            const float wCr = wAr * wBr - wAi * wBi;
            const float wCi = wAr * wBi + wAi * wBr;
            const float er = d0r - d1i, ei = d0i + d1r;
            zr = er * wCr - ei * wCi;
            zi = er * wCi + ei * wCr;
        }
    }

    // ---- Shfl stages H=16..1 (one register) ----
#pragma unroll
    for (int h = 16; h >= 1; h >>= 1) {
        const int step = 16 / h;
        float twn, twc;
        __sincosf(-TWO_PI * (float)(step * (l & (h - 1))) * (1.0f / 32.0f),
                  &twn, &twc);
        const bool bot = (l & h) != 0;
        const float pr = __shfl_xor_sync(0xffffffffu, zr, h);
        const float pi = __shfl_xor_sync(0xffffffffu, zi, h);
        const float dr = pr - zr;
        const float di = pi - zi;
        const float tr = fmaf(dr, twc, -di * twn);
        const float ti = fmaf(dr, twn,  di * twc);
        zr = bot ? tr : (zr + pr);
        zi = bot ? ti : (zi + pi);
    }

    // ---- Stash Z by position (s1 is dead; reuse) ----
    s1[tid] = make_float2(zr, zi);
    __syncthreads();

    // ---- Unpack + emit: f = bitrev9(tid); emit if f <= 256 ----
    const int f = bitrev9r(tid);
    if (f <= 256) {
        const int fb   = (512 - f) & 511;
        const int posb = bitrev9r(fb);
        const float2 Y = s1[posb];

        const float F0r = 0.5f * (zr + Y.x);
        const float F0i = 0.5f * (zi - Y.y);
        const float F1r = 0.5f * (zi + Y.y);
        const float F1i = 0.5f * (Y.x - zr);

        float sp, cp;                 // shift e^{+2*pi*i*frac*f/512}
        __sincosf(TWO_PI * frac * (float)f * (1.0f / 512.0f), &sp, &cp);

        const float re0 = fmaf(F0r, cp, -F0i * sp);
        const float im0 = fmaf(F0r, sp,  F0i * cp);
        const float re1 = fmaf(F1r, cp, -F1i * sp);
        const float im1 = fmaf(F1r, sp,  F1i * cp);

        const int o0 = ((2 * p) * NF + f) * NT + t;
        const int o1 = o0 + NF * NT;
        out[o0]       = sqrtf(fmaf(re0, re0, im0 * im0)) + 1.1920929e-7f;
        out[BFT + o0] = re0;
        out[o1]       = sqrtf(fmaf(re1, re1, im1 * im1)) + 1.1920929e-7f;
        out[BFT + o1] = re1;
    }
}

// ---------------------------------------------------------------------------
extern "C" void kernel_launch(void* const* d_in, const int* in_sizes, int n_in,
                              void* d_out, int out_size) {
    // x is the unique large input; win_length is the middle input under both
    // insertion and alphabetical order; strides is the remaining small one.
    int ix = 0;
    for (int i = 1; i < n_in; ++i)
        if (in_sizes[i] > in_sizes[ix]) ix = i;
    const float* x  = (const float*)d_in[ix];
    const float* wl = (const float*)d_in[1];
    const float* st = (const float*)d_in[(ix == 0) ? 2 : 0];
    float* out = (float*)d_out;

    dim3 grid(NT, 2);
    adstft_kernel<<<grid, 512>>>(x, wl, st, out);
}

// round 16
// speedup vs baseline: 1.0489x; 1.0489x over previous
#include <cuda_runtime.h>

// Fixed problem shapes: B=4, L=80000, N=512, F=257, STRIDE=256 -> T=311
#define NB  4
#define NL  80000
#define NN  512
#define NF  257
#define NT  311
#define BFT (NB * NF * NT)   // 319708

#define TWO_PI 6.2831853071795864769f

__device__ __forceinline__ int bitrev4r(int v) {
    return ((v & 1) << 3) | ((v & 2) << 1) | ((v & 4) >> 1) | ((v & 8) >> 3);
}
__device__ __forceinline__ int bitrev5r(int v) {
    return ((v & 1) << 4) | ((v & 2) << 2) | (v & 4) | ((v & 8) >> 2) | ((v & 16) >> 4);
}
__device__ __forceinline__ int bitrev9r(int v) {
    return bitrev4r(v >> 5) | (bitrev5r(v & 31) << 4);
}

// ---------------------------------------------------------------------------
// Block = 256 threads (8 warps) per (frame t, batch-PAIR p); grid (NT, 2).
// Structure identical to verified round 14 (real-pair packed 512-FFT):
//  H=256,128 fused radix-4 smem exchange; H=64 cross-warp smem butterfly;
//  H=32 register butterfly; H=16..1 shfl-xor butterflies; conjugate unpack.
// Round-16 deltas (instruction cuts only):
//  - shfl-stage twiddles via double-angle recurrence (1 sincos instead of 5):
//      theta_{h/2} = 2*theta_h + pi*[l & (h/2)]  ->  c,s doubling + sign flip
//  - window-tap division replaced by one __fdividef-derived scale
// Output layout: floats [0,BFT) = spec; [BFT,2*BFT) = real(stft).
// ---------------------------------------------------------------------------
__global__ void __launch_bounds__(256, 6)
adstft_kernel(const float* __restrict__ x,
              const float* __restrict__ wlp,
              const float* __restrict__ stp,
              float* __restrict__ out) {
    __shared__ float2 s1[16][32];   // radix-4 input; later reused as Z stash
    __shared__ float2 s2[16][32];   // H=64 exchange

    const int t = blockIdx.x;
    const int p = blockIdx.y;       // batch pair: batches 2p, 2p+1
    const int m = threadIdx.x >> 5;
    const int l = threadIdx.x & 31;

    const float wl = fminf(fmaxf(wlp[0], 25.6f), 512.0f);   // WIN_MIN..WIN_MAX
    const float st = fminf(fmaxf(stp[0], 0.0f), 512.0f);    // STRIDE_MIN..MAX
    const float frame = st * (float)t;                       // == cumsum for integral st
    const float flo   = floorf(frame);
    const float frac  = frame - flo;
    const int   i0    = (int)flo;
    const float hi    = ceilf ((511.0f + wl) * 0.5f);
    const float lo    = floorf((511.0f - wl) * 0.5f);
    const float woff  = (wl - 511.0f) * 0.5f;
    const float angs  = __fdividef(TWO_PI, wl);              // tap angle scale

    // ---- Load + window: z = g_{2p} + i*g_{2p+1} ----
    {
        const float* xb0 = x + (2 * p) * NL;
        const float* xb1 = xb0 + NL;
#pragma unroll
        for (int k = 0; k < 2; ++k) {
            const int n   = 32 * (2 * m + k) + l;
            const int idx = i0 + n;
            const bool ok = ((unsigned)idx < (unsigned)NL);
            const float v0 = ok ? xb0[idx] : 0.0f;
            const float v1 = ok ? xb1[idx] : 0.0f;
            const float base = (float)n - frac;
            float tap = 0.0f;
            if (!(base >= hi || base <= lo))
                tap = (0.5f - 0.5f * __cosf((base + woff) * angs))
                      * 0.00390625f;                         // / N * 2
            s1[2 * m + k][l] = make_float2(v0 * tap, v1 * tap);
        }
    }
    __syncthreads();

    // ---- Fused radix-4 cross-warp stages (H=256 then H=128) ----
    float zr[2], zi[2];
    {
        const int q = m >> 1;                         // warp-uniform quartet slot
        float wlr, wli;                               // w(l) = e^{-2*pi*i*l/512}
        __sincosf(-TWO_PI * (float)l * (1.0f / 512.0f), &wli, &wlr);
        const float KC[4] = {1.0f, 0.92387953f,  0.70710678f,  0.38268343f};
        const float KS[4] = {0.0f, -0.38268343f, -0.70710678f, -0.92387953f};
#pragma unroll
        for (int k = 0; k < 2; ++k) {
            const int c = 2 * (m & 1) + k;            // kk mod 4
            const float wAr = wlr * KC[c] - wli * KS[c];
            const float wAi = wlr * KS[c] + wli * KC[c];

            const float2 c0 = s1[c     ][l];
            const float2 c1 = s1[c +  4][l];
            const float2 c2 = s1[c +  8][l];
            const float2 c3 = s1[c + 12][l];
            const float s0r = c0.x + c2.x, s0i = c0.y + c2.y;
            const float s1r = c1.x + c3.x, s1i = c1.y + c3.y;
            const float d0r = c0.x - c2.x, d0i = c0.y - c2.y;
            const float d1r = c1.x - c3.x, d1i = c1.y - c3.y;

            float rr, ri;
            if (q == 0) {                       // B0 = s0 + s1
                rr = s0r + s1r; ri = s0i + s1i;
            } else if (q == 1) {                // B1 = (s0 - s1) * wA^2
                const float wBr = wAr * wAr - wAi * wAi;
                const float wBi = 2.0f * wAr * wAi;
                const float er = s0r - s1r, ei = s0i - s1i;
                rr = er * wBr - ei * wBi;
                ri = er * wBi + ei * wBr;
            } else if (q == 2) {                // B2 = wA * (d0 - i*d1)
                const float er = d0r + d1i, ei = d0i - d1r;
                rr = er * wAr - ei * wAi;
                ri = er * wAi + ei * wAr;
            } else {                            // B3 = wA^3 * (d0 + i*d1)
                const float wBr = wAr * wAr - wAi * wAi;
                const float wBi = 2.0f * wAr * wAi;
                const float wCr = wAr * wBr - wAi * wBi;
                const float wCi = wAr * wBi + wAi * wBr;
                const float er = d0r - d1i, ei = d0i + d1r;
                rr = er * wCr - ei * wCi;
                ri = er * wCi + ei * wCr;
            }
            zr[k] = rr; zi[k] = ri;
        }
    }

    // ---- H=64: cross-warp butterfly via s2 (pairs kk, kk^2 <=> m, m^1) ----
    s2[2 * m    ][l] = make_float2(zr[0], zi[0]);
    s2[2 * m + 1][l] = make_float2(zr[1], zi[1]);
    __syncthreads();
    {
        float t0i, t0r;                 // k=0: e^{-2*pi*i*l/128}; k=1: -i * that
        __sincosf(-TWO_PI * (float)l * (1.0f / 128.0f), &t0i, &t0r);
        const float t1r = t0i;
        const float t1i = -t0r;
        const bool top = ((m & 1) == 0);
#pragma unroll
        for (int k = 0; k < 2; ++k) {
            const float2 pp = s2[(2 * m + k) ^ 2][l];
            if (top) {
                zr[k] += pp.x;
                zi[k] += pp.y;
            } else {
                const float dr = pp.x - zr[k];
                const float di = pp.y - zi[k];
                const float Tr = k ? t1r : t0r;
                const float Ti = k ? t1i : t0i;
                zr[k] = fmaf(dr, Tr, -di * Ti);
                zi[k] = fmaf(dr, Ti,  di * Tr);
            }
        }
    }

    // ---- H=32: register butterfly ----
    {
        float sn, c;
        __sincosf(-TWO_PI * (float)l * (1.0f / 64.0f), &sn, &c);
        const float dr = zr[0] - zr[1];
        const float di = zi[0] - zi[1];
        zr[0] += zr[1];
        zi[0] += zi[1];
        zr[1] = fmaf(dr, c,  -di * sn);
        zi[1] = fmaf(dr, sn,  di * c);
    }

    // ---- Shfl stages H=16..1, twiddles by double-angle recurrence ----
    {
        float twc, twn;                 // stage h=16: theta = -2*pi*(l&15)/32
        __sincosf(-TWO_PI * (float)(l & 15) * (1.0f / 32.0f), &twn, &twc);
#pragma unroll
        for (int s = 0; s < 5; ++s) {
            const int h = 16 >> s;
            const bool bot = (l & h) != 0;
#pragma unroll
            for (int k = 0; k < 2; ++k) {
                const float pr = __shfl_xor_sync(0xffffffffu, zr[k], h);
                const float pi = __shfl_xor_sync(0xffffffffu, zi[k], h);
                const float dr = pr - zr[k];
                const float di = pi - zi[k];
                const float tr = fmaf(dr, twc, -di * twn);
                const float ti = fmaf(dr, twn,  di * twc);
                zr[k] = bot ? tr : (zr[k] + pr);
                zi[k] = bot ? ti : (zi[k] + pi);
            }
            if (s < 4) {
                // theta' = 2*theta + pi*[l & (h/2)]
                const float c2 = fmaf(2.0f * twc, twc, -1.0f);
                const float s2d = 2.0f * twc * twn;
                const bool flip = (l & (h >> 1)) != 0;
                twc = flip ? -c2  : c2;
                twn = flip ? -s2d : s2d;
            }
        }
    }

    // ---- Stash all Z by position pos = 32*kk + l (s1 is dead; reuse) ----
    float* sZr = (float*)s1;            // [512]
    float* sZi = sZr + 512;             // [512]
    sZr[64 * m + l]      = zr[0];
    sZi[64 * m + l]      = zi[0];
    sZr[64 * m + 32 + l] = zr[1];
    sZi[64 * m + 32 + l] = zi[1];
    __syncthreads();

    // ---- Unpack + emit: each lane owns one f (r13/r14 assignment) ----
    const int q5   = bitrev5r(l);
    const int brm3 = ((m & 1) << 2) | (m & 2) | ((m & 4) >> 2);   // bitrev3(m)

    const int fown = ((l & 1) == 0) ? ((q5 << 4) | brm3)
                                    : ((((q5 - 16) << 4) | brm3) | 8);
    const int b0 = 2 * p;

    const int nEmit = (m == 0 && l == 1) ? 2 : 1;
    for (int e = 0; e < nEmit; ++e) {
        const int f = (e == 0) ? fown : 256;

        const int pos  = (bitrev4r(f & 15) << 5) | bitrev5r(f >> 4);
        const int fb   = (512 - f) & 511;
        const int posb = (bitrev4r(fb & 15) << 5) | bitrev5r(fb >> 4);

        const float Zr = sZr[pos],  Zi = sZi[pos];
        const float Yr = sZr[posb], Yi = sZi[posb];

        const float F0r = 0.5f * (Zr + Yr);
        const float F0i = 0.5f * (Zi - Yi);
        const float F1r = 0.5f * (Zi + Yi);
        const float F1i = 0.5f * (Yr - Zr);

        float sp, cp;                   // shift e^{+2*pi*i*frac*f/512}
        __sincosf(TWO_PI * frac * (float)f * (1.0f / 512.0f), &sp, &cp);

        const float re0 = fmaf(F0r, cp, -F0i * sp);
        const float im0 = fmaf(F0r, sp,  F0i * cp);
        const float re1 = fmaf(F1r, cp, -F1i * sp);
        const float im1 = fmaf(F1r, sp,  F1i * cp);

        const int o0 = (b0 * NF + f) * NT + t;
        const int o1 = o0 + NF * NT;
        out[o0]       = sqrtf(fmaf(re0, re0, im0 * im0)) + 1.1920929e-7f;
        out[BFT + o0] = re0;
        out[o1]       = sqrtf(fmaf(re1, re1, im1 * im1)) + 1.1920929e-7f;
        out[BFT + o1] = re1;
    }
}

// ---------------------------------------------------------------------------
extern "C" void kernel_launch(void* const* d_in, const int* in_sizes, int n_in,
                              void* d_out, int out_size) {
    // x is the unique large input; win_length is the middle input under both
    // insertion and alphabetical order; strides is the remaining small one.
    int ix = 0;
    for (int i = 1; i < n_in; ++i)
        if (in_sizes[i] > in_sizes[ix]) ix = i;
    const float* x  = (const float*)d_in[ix];
    const float* wl = (const float*)d_in[1];
    const float* st = (const float*)d_in[(ix == 0) ? 2 : 0];
    float* out = (float*)d_out;

    dim3 grid(NT, 2);
    adstft_kernel<<<grid, 256>>>(x, wl, st, out);
}